// round 1
// baseline (speedup 1.0000x reference)
#include <cuda_runtime.h>
#include <math.h>

// Stacked LSTM: B=64, T=512, D=256, H=512, 3 layers.
// Single persistent kernel, software grid barrier, one barrier per timestep.
// Block bc owns hidden units [bc*4, bc*4+4): computes 16 z-columns (4 gates x 4
// units) per step as a 64x16xK GEMM (input projection folded: K = D+H or H+H),
// then applies gates. Cell state c lives in a register per (b, j) thread.

#define Bsz 64
#define Tsz 512
#define Dsz 256
#define Hsz 512
#define Gsz 2048
#define NBLK 128
#define NTHR 256
#define KC 32

// Scratch (device globals: the sanctioned no-alloc path)
__device__ float g_seqA[(size_t)Bsz * Tsz * Hsz];  // 64 MB
__device__ float g_seqB[(size_t)Bsz * Tsz * Hsz];  // 64 MB
__device__ float g_hbuf[2][Bsz * Hsz];             // ping-pong hidden state
__device__ unsigned g_count = 0;
__device__ volatile unsigned g_gen = 0;

__device__ __forceinline__ void grid_sync() {
    __threadfence();          // make this thread's prior writes device-visible
    __syncthreads();          // all block threads' writes ordered before arrival
    if (threadIdx.x == 0) {
        unsigned my = g_gen;  // read generation BEFORE arriving
        if (atomicAdd(&g_count, 1u) == NBLK - 1) {
            g_count = 0;
            __threadfence();
            atomicAdd((unsigned*)&g_gen, 1u);   // release
        } else {
            while (g_gen == my) { __nanosleep(32); }
        }
    }
    __syncthreads();
}

extern "C" __global__ void __launch_bounds__(NTHR, 1)
lstm_kernel(const float* __restrict__ x0,
            const float* __restrict__ W0, const float* __restrict__ U0, const float* __restrict__ b0,
            const float* __restrict__ W1, const float* __restrict__ U1, const float* __restrict__ b1,
            const float* __restrict__ W2, const float* __restrict__ U2, const float* __restrict__ b2,
            float* __restrict__ out)
{
    // smem: A tiles per k-split group ([64 rows][33] pad -> conflict-free LDS),
    // U strips per group, post-reduction z, bias. Total ~46 KB (static).
    __shared__ float a_s[4][64][33];
    __shared__ float u_s[4][KC][16];
    __shared__ float zs[16 * 65];
    __shared__ float bias_s[16];

    const int tid    = threadIdx.x;
    const int bc     = blockIdx.x;
    const int ksplit = tid >> 6;    // 0..3  K-split group
    const int ot     = tid & 63;    // thread within group
    const int rg     = ot >> 2;     // 0..15 row group (4 rows each)
    const int cg     = ot & 3;      // 0..3  col group = gate (4 cols each)
    const int j0     = bc * 4;      // hidden-unit base for this block
    const int gb     = tid >> 2;    // gate phase: batch row 0..63
    const int gj     = tid & 3;     // gate phase: unit offset 0..3

    for (int layer = 0; layer < 3; layer++) {
        const float* Wl = (layer == 0) ? W0 : ((layer == 1) ? W1 : W2);
        const float* Ul = (layer == 0) ? U0 : ((layer == 1) ? U1 : U2);
        const float* bl = (layer == 0) ? b0 : ((layer == 1) ? b1 : b2);
        const float* xsrc = (layer == 0) ? x0 : ((layer == 1) ? g_seqA : g_seqB);
        float* seqout = (layer == 0) ? g_seqA : ((layer == 1) ? g_seqB : (float*)nullptr);
        const int K_in = (layer == 0) ? Dsz : Hsz;
        const int nchunkpg = (K_in + Hsz) / KC / 4;   // chunks per k-split group (6 or 8)

        if (tid < 16) bias_s[tid] = bl[(tid >> 2) * Hsz + j0 + (tid & 3)];
        g_hbuf[0][gb * Hsz + j0 + gj] = 0.0f;   // each block zeroes its own slice
        float c_reg = 0.0f;
        float hval  = 0.0f;
        int cur = 0;
        grid_sync();

        for (int t = 0; t < Tsz; t++) {
            float acc[4][4] = {};
            const float* hsrc = g_hbuf[cur];

            for (int cc = 0; cc < nchunkpg; cc++) {
                const int kc = (ksplit * nchunkpg + cc) * KC;
                // ---- stage A: 64 rows x KC (x part or h part; chunks never straddle)
                {
                    const int bq = ot >> 3;        // 0..7
                    const int k4 = (ot & 7) * 4;   // 0,4,...,28
                    if (kc < K_in) {
                        #pragma unroll
                        for (int rep = 0; rep < 8; rep++) {
                            int b = rep * 8 + bq;
                            float4 v = *(const float4*)(xsrc + ((size_t)(b * Tsz + t)) * K_in + kc + k4);
                            float* d = &a_s[ksplit][b][k4];
                            d[0] = v.x; d[1] = v.y; d[2] = v.z; d[3] = v.w;
                        }
                    } else {
                        #pragma unroll
                        for (int rep = 0; rep < 8; rep++) {
                            int b = rep * 8 + bq;
                            float4 v = *(const float4*)(hsrc + b * Hsz + (kc - K_in) + k4);
                            float* d = &a_s[ksplit][b][k4];
                            d[0] = v.x; d[1] = v.y; d[2] = v.z; d[3] = v.w;
                        }
                    }
                }
                // ---- stage U: KC x 16 (4 gate strips of 4 consecutive cols)
                {
                    const int strip = ot & 3;
                    #pragma unroll
                    for (int rep = 0; rep < 2; rep++) {
                        int k = rep * 16 + (ot >> 2);
                        int gk = kc + k;
                        const float* wrow = (gk < K_in) ? (Wl + (size_t)gk * Gsz)
                                                        : (Ul + (size_t)(gk - K_in) * Gsz);
                        float4 v = *(const float4*)(wrow + strip * Hsz + j0);
                        *(float4*)&u_s[ksplit][k][strip * 4] = v;
                    }
                }
                __syncthreads();
                // ---- compute: 4x4 register tile over this K chunk
                const int r4 = rg * 4;
                #pragma unroll 8
                for (int k = 0; k < KC; k++) {
                    float4 uv = *(const float4*)&u_s[ksplit][k][cg * 4];
                    float a0 = a_s[ksplit][r4 + 0][k];
                    float a1 = a_s[ksplit][r4 + 1][k];
                    float a2 = a_s[ksplit][r4 + 2][k];
                    float a3 = a_s[ksplit][r4 + 3][k];
                    acc[0][0] += a0 * uv.x; acc[0][1] += a0 * uv.y; acc[0][2] += a0 * uv.z; acc[0][3] += a0 * uv.w;
                    acc[1][0] += a1 * uv.x; acc[1][1] += a1 * uv.y; acc[1][2] += a1 * uv.z; acc[1][3] += a1 * uv.w;
                    acc[2][0] += a2 * uv.x; acc[2][1] += a2 * uv.y; acc[2][2] += a2 * uv.z; acc[2][3] += a2 * uv.w;
                    acc[3][0] += a3 * uv.x; acc[3][1] += a3 * uv.y; acc[3][2] += a3 * uv.z; acc[3][3] += a3 * uv.w;
                }
                __syncthreads();
            }

            // ---- k-split reduction (reuse a_s regions, [16 cols][64 rows] pad 65)
            {
                float* zr = &a_s[ksplit][0][0];
                #pragma unroll
                for (int u = 0; u < 4; u++) {
                    #pragma unroll
                    for (int v = 0; v < 4; v++) {
                        zr[(cg * 4 + v) * 65 + (rg * 4 + u)] = acc[u][v];
                    }
                }
            }
            __syncthreads();
            {
                const float* z0 = &a_s[0][0][0];
                const float* z1 = &a_s[1][0][0];
                const float* z2 = &a_s[2][0][0];
                const float* z3 = &a_s[3][0][0];
                #pragma unroll
                for (int e = 0; e < 4; e++) {
                    int idx = tid * 4 + e;
                    int c = idx >> 6, r = idx & 63;
                    int o = c * 65 + r;
                    zs[o] = z0[o] + z1[o] + z2[o] + z3[o] + bias_s[c];
                }
            }
            __syncthreads();

            // ---- gates: one thread per (batch, hidden-unit)
            {
                float zi = zs[(0 * 4 + gj) * 65 + gb];
                float zf = zs[(1 * 4 + gj) * 65 + gb];
                float zg = zs[(2 * 4 + gj) * 65 + gb];
                float zo = zs[(3 * 4 + gj) * 65 + gb];
                float ig = 1.0f / (1.0f + expf(-zi));
                float fg = 1.0f / (1.0f + expf(-zf));
                float gg = tanhf(zg);
                float og = 1.0f / (1.0f + expf(-zo));
                c_reg = fg * c_reg + ig * gg;
                hval  = og * tanhf(c_reg);
                g_hbuf[cur ^ 1][gb * Hsz + j0 + gj] = hval;
                if (seqout) seqout[((size_t)(gb * Tsz + t)) * Hsz + j0 + gj] = hval;
            }
            cur ^= 1;
            grid_sync();
        }

        // ---- layer finals. Output layout: [out(=h2) | h0 | c0 | h1 | c1 | h2 | c2]
        {
            size_t off = (size_t)gb * Hsz + j0 + gj;
            const size_t S = (size_t)Bsz * Hsz;  // 32768
            if (layer == 0)      { out[1 * S + off] = hval; out[2 * S + off] = c_reg; }
            else if (layer == 1) { out[3 * S + off] = hval; out[4 * S + off] = c_reg; }
            else                 { out[off] = hval; out[5 * S + off] = hval; out[6 * S + off] = c_reg; }
        }
        grid_sync();
    }
}

extern "C" void kernel_launch(void* const* d_in, const int* in_sizes, int n_in,
                              void* d_out, int out_size) {
    (void)in_sizes; (void)n_in; (void)out_size;
    lstm_kernel<<<NBLK, NTHR>>>(
        (const float*)d_in[0],
        (const float*)d_in[1], (const float*)d_in[2], (const float*)d_in[3],
        (const float*)d_in[4], (const float*)d_in[5], (const float*)d_in[6],
        (const float*)d_in[7], (const float*)d_in[8], (const float*)d_in[9],
        (float*)d_out);
}

// round 2
// speedup vs baseline: 1.0005x; 1.0005x over previous
#include <cuda_runtime.h>
#include <math.h>

// Stacked LSTM: B=64, T=512, D=256, H=512, 3 layers.
// Single persistent kernel, software grid barrier, one barrier per timestep.
// Block bc owns hidden units [bc*4, bc*4+4): computes 16 z-columns (4 gates x 4
// units) per step as a 64x16xK GEMM (input projection folded: K = D+H or H+H),
// then applies gates. Cell state c lives in a register per (b, j) thread.

#define Bsz 64
#define Tsz 512
#define Dsz 256
#define Hsz 512
#define Gsz 2048
#define NBLK 128
#define NTHR 256
#define KC 32

// Scratch (device globals: the sanctioned no-alloc path)
__device__ float g_seqA[(size_t)Bsz * Tsz * Hsz];  // 64 MB
__device__ float g_seqB[(size_t)Bsz * Tsz * Hsz];  // 64 MB
__device__ float g_hbuf[2][Bsz * Hsz];             // ping-pong hidden state
__device__ unsigned g_count = 0;
__device__ volatile unsigned g_gen = 0;

__device__ __forceinline__ void grid_sync() {
    __threadfence();          // make this thread's prior writes device-visible
    __syncthreads();          // all block threads' writes ordered before arrival
    if (threadIdx.x == 0) {
        unsigned my = g_gen;  // read generation BEFORE arriving
        if (atomicAdd(&g_count, 1u) == NBLK - 1) {
            g_count = 0;
            __threadfence();
            atomicAdd((unsigned*)&g_gen, 1u);   // release
        } else {
            while (g_gen == my) { __nanosleep(32); }
        }
    }
    __syncthreads();
}

extern "C" __global__ void __launch_bounds__(NTHR, 1)
lstm_kernel(const float* __restrict__ x0,
            const float* __restrict__ W0, const float* __restrict__ U0, const float* __restrict__ b0,
            const float* __restrict__ W1, const float* __restrict__ U1, const float* __restrict__ b1,
            const float* __restrict__ W2, const float* __restrict__ U2, const float* __restrict__ b2,
            float* __restrict__ out)
{
    // smem: A tiles per k-split group ([64 rows][33] pad -> conflict-free LDS),
    // U strips per group, post-reduction z, bias. Total ~46 KB (static).
    __shared__ float a_s[4][64][33];
    __shared__ float u_s[4][KC][16];
    __shared__ float zs[16 * 65];
    __shared__ float bias_s[16];

    const int tid    = threadIdx.x;
    const int bc     = blockIdx.x;
    const int ksplit = tid >> 6;    // 0..3  K-split group
    const int ot     = tid & 63;    // thread within group
    const int rg     = ot >> 2;     // 0..15 row group (4 rows each)
    const int cg     = ot & 3;      // 0..3  col group = gate (4 cols each)
    const int j0     = bc * 4;      // hidden-unit base for this block
    const int gb     = tid >> 2;    // gate phase: batch row 0..63
    const int gj     = tid & 3;     // gate phase: unit offset 0..3

    for (int layer = 0; layer < 3; layer++) {
        const float* Wl = (layer == 0) ? W0 : ((layer == 1) ? W1 : W2);
        const float* Ul = (layer == 0) ? U0 : ((layer == 1) ? U1 : U2);
        const float* bl = (layer == 0) ? b0 : ((layer == 1) ? b1 : b2);
        const float* xsrc = (layer == 0) ? x0 : ((layer == 1) ? g_seqA : g_seqB);
        float* seqout = (layer == 0) ? g_seqA : ((layer == 1) ? g_seqB : (float*)nullptr);
        const int K_in = (layer == 0) ? Dsz : Hsz;
        const int nchunkpg = (K_in + Hsz) / KC / 4;   // chunks per k-split group (6 or 8)

        if (tid < 16) bias_s[tid] = bl[(tid >> 2) * Hsz + j0 + (tid & 3)];
        g_hbuf[0][gb * Hsz + j0 + gj] = 0.0f;   // each block zeroes its own slice
        float c_reg = 0.0f;
        float hval  = 0.0f;
        int cur = 0;
        grid_sync();

        for (int t = 0; t < Tsz; t++) {
            float acc[4][4] = {};
            const float* hsrc = g_hbuf[cur];

            for (int cc = 0; cc < nchunkpg; cc++) {
                const int kc = (ksplit * nchunkpg + cc) * KC;
                // ---- stage A: 64 rows x KC (x part or h part; chunks never straddle)
                {
                    const int bq = ot >> 3;        // 0..7
                    const int k4 = (ot & 7) * 4;   // 0,4,...,28
                    if (kc < K_in) {
                        #pragma unroll
                        for (int rep = 0; rep < 8; rep++) {
                            int b = rep * 8 + bq;
                            float4 v = *(const float4*)(xsrc + ((size_t)(b * Tsz + t)) * K_in + kc + k4);
                            float* d = &a_s[ksplit][b][k4];
                            d[0] = v.x; d[1] = v.y; d[2] = v.z; d[3] = v.w;
                        }
                    } else {
                        #pragma unroll
                        for (int rep = 0; rep < 8; rep++) {
                            int b = rep * 8 + bq;
                            float4 v = *(const float4*)(hsrc + b * Hsz + (kc - K_in) + k4);
                            float* d = &a_s[ksplit][b][k4];
                            d[0] = v.x; d[1] = v.y; d[2] = v.z; d[3] = v.w;
                        }
                    }
                }
                // ---- stage U: KC x 16 (4 gate strips of 4 consecutive cols)
                {
                    const int strip = ot & 3;
                    #pragma unroll
                    for (int rep = 0; rep < 2; rep++) {
                        int k = rep * 16 + (ot >> 2);
                        int gk = kc + k;
                        const float* wrow = (gk < K_in) ? (Wl + (size_t)gk * Gsz)
                                                        : (Ul + (size_t)(gk - K_in) * Gsz);
                        float4 v = *(const float4*)(wrow + strip * Hsz + j0);
                        *(float4*)&u_s[ksplit][k][strip * 4] = v;
                    }
                }
                __syncthreads();
                // ---- compute: 4x4 register tile over this K chunk
                const int r4 = rg * 4;
                #pragma unroll 8
                for (int k = 0; k < KC; k++) {
                    float4 uv = *(const float4*)&u_s[ksplit][k][cg * 4];
                    float a0 = a_s[ksplit][r4 + 0][k];
                    float a1 = a_s[ksplit][r4 + 1][k];
                    float a2 = a_s[ksplit][r4 + 2][k];
                    float a3 = a_s[ksplit][r4 + 3][k];
                    acc[0][0] += a0 * uv.x; acc[0][1] += a0 * uv.y; acc[0][2] += a0 * uv.z; acc[0][3] += a0 * uv.w;
                    acc[1][0] += a1 * uv.x; acc[1][1] += a1 * uv.y; acc[1][2] += a1 * uv.z; acc[1][3] += a1 * uv.w;
                    acc[2][0] += a2 * uv.x; acc[2][1] += a2 * uv.y; acc[2][2] += a2 * uv.z; acc[2][3] += a2 * uv.w;
                    acc[3][0] += a3 * uv.x; acc[3][1] += a3 * uv.y; acc[3][2] += a3 * uv.z; acc[3][3] += a3 * uv.w;
                }
                __syncthreads();
            }

            // ---- k-split reduction (reuse a_s regions, [16 cols][64 rows] pad 65)
            {
                float* zr = &a_s[ksplit][0][0];
                #pragma unroll
                for (int u = 0; u < 4; u++) {
                    #pragma unroll
                    for (int v = 0; v < 4; v++) {
                        zr[(cg * 4 + v) * 65 + (rg * 4 + u)] = acc[u][v];
                    }
                }
            }
            __syncthreads();
            {
                const float* z0 = &a_s[0][0][0];
                const float* z1 = &a_s[1][0][0];
                const float* z2 = &a_s[2][0][0];
                const float* z3 = &a_s[3][0][0];
                #pragma unroll
                for (int e = 0; e < 4; e++) {
                    int idx = tid * 4 + e;
                    int c = idx >> 6, r = idx & 63;
                    int o = c * 65 + r;
                    zs[o] = z0[o] + z1[o] + z2[o] + z3[o] + bias_s[c];
                }
            }
            __syncthreads();

            // ---- gates: one thread per (batch, hidden-unit)
            {
                float zi = zs[(0 * 4 + gj) * 65 + gb];
                float zf = zs[(1 * 4 + gj) * 65 + gb];
                float zg = zs[(2 * 4 + gj) * 65 + gb];
                float zo = zs[(3 * 4 + gj) * 65 + gb];
                float ig = 1.0f / (1.0f + expf(-zi));
                float fg = 1.0f / (1.0f + expf(-zf));
                float gg = tanhf(zg);
                float og = 1.0f / (1.0f + expf(-zo));
                c_reg = fg * c_reg + ig * gg;
                hval  = og * tanhf(c_reg);
                g_hbuf[cur ^ 1][gb * Hsz + j0 + gj] = hval;
                if (seqout) seqout[((size_t)(gb * Tsz + t)) * Hsz + j0 + gj] = hval;
            }
            cur ^= 1;
            grid_sync();
        }

        // ---- layer finals. Output layout: [out(=h2) | h0 | c0 | h1 | c1 | h2 | c2]
        {
            size_t off = (size_t)gb * Hsz + j0 + gj;
            const size_t S = (size_t)Bsz * Hsz;  // 32768
            if (layer == 0)      { out[1 * S + off] = hval; out[2 * S + off] = c_reg; }
            else if (layer == 1) { out[3 * S + off] = hval; out[4 * S + off] = c_reg; }
            else                 { out[off] = hval; out[5 * S + off] = hval; out[6 * S + off] = c_reg; }
        }
        grid_sync();
    }
}

extern "C" void kernel_launch(void* const* d_in, const int* in_sizes, int n_in,
                              void* d_out, int out_size) {
    (void)in_sizes; (void)n_in; (void)out_size;
    lstm_kernel<<<NBLK, NTHR>>>(
        (const float*)d_in[0],
        (const float*)d_in[1], (const float*)d_in[2], (const float*)d_in[3],
        (const float*)d_in[4], (const float*)d_in[5], (const float*)d_in[6],
        (const float*)d_in[7], (const float*)d_in[8], (const float*)d_in[9],
        (float*)d_out);
}

// round 3
// speedup vs baseline: 1.5252x; 1.5244x over previous
#include <cuda_runtime.h>

// Stacked LSTM: B=64, T=512, D=256, H=512, 3 layers. fp32.
// Persistent kernel, 128 blocks x 256 threads, one grid barrier per timestep.
// Block bc owns 4 hidden units => 16 z-columns. Per step: 64x16xK GEMM
// (K = D+H or 2H), 4-way K-split inside the block, 4x4 register tiles.
// Weights (Kx16) stay resident in smem for the whole layer (loaded once).
// A (the [x_t ; h] panel) is double-buffered: LDG->regs overlapped with
// compute, STS into the idle buffer, one __syncthreads per chunk.

#define Bsz 64
#define Tsz 512
#define Dsz 256
#define Hsz 512
#define Gsz 2048
#define NBLK 128
#define NTHR 256
#define KC 32

// dynamic smem layout (floats):
//   w_s   [1024][16]              16384
//   a_s   [2][4][64][36]          18432
//   zred  [4][64][17]              4352
//   bias  [16]                       16
#define SM_WS   0
#define SM_AS   16384
#define SM_ZRED (16384 + 18432)
#define SM_BIAS (16384 + 18432 + 4352)
#define SMEM_FLOATS (16384 + 18432 + 4352 + 16)
#define SMEM_BYTES (SMEM_FLOATS * 4)

__device__ float g_seqA[(size_t)Bsz * Tsz * Hsz];  // 64 MB
__device__ float g_seqB[(size_t)Bsz * Tsz * Hsz];  // 64 MB
__device__ float g_hbuf[2][Bsz * Hsz];
__device__ unsigned g_count = 0;
__device__ volatile unsigned g_gen = 0;

__device__ __forceinline__ void grid_sync() {
    __threadfence();
    __syncthreads();
    if (threadIdx.x == 0) {
        unsigned my = g_gen;
        if (atomicAdd(&g_count, 1u) == NBLK - 1) {
            g_count = 0;
            __threadfence();
            atomicAdd((unsigned*)&g_gen, 1u);
        } else {
            while (g_gen == my) { __nanosleep(32); }
        }
    }
    __syncthreads();
}

__device__ __forceinline__ float fsig(float x) {
    // saturation-safe fast sigmoid
    return __fdividef(1.0f, 1.0f + __expf(-x));
}
__device__ __forceinline__ float ftanh(float x) {
    // tanh(x) = 1 - 2/(e^{2x}+1); e->inf => 1, e->0 => -1 (no NaN)
    float e = __expf(2.0f * x);
    return 1.0f - __fdividef(2.0f, e + 1.0f);
}

extern "C" __global__ void __launch_bounds__(NTHR, 1)
lstm_kernel(const float* __restrict__ x0,
            const float* __restrict__ W0, const float* __restrict__ U0, const float* __restrict__ b0,
            const float* __restrict__ W1, const float* __restrict__ U1, const float* __restrict__ b1,
            const float* __restrict__ W2, const float* __restrict__ U2, const float* __restrict__ b2,
            float* __restrict__ out)
{
    extern __shared__ float smem[];
    float* w_s    = smem + SM_WS;     // [k][16], k global within [0, Ktot)
    float* a_s    = smem + SM_AS;     // [buf][ks][row][36]
    float* zred   = smem + SM_ZRED;   // [ks][row][17]
    float* bias_s = smem + SM_BIAS;   // [16]

    const int tid = threadIdx.x;
    const int bc  = blockIdx.x;
    const int ks  = tid >> 6;        // 0..3 K-split group
    const int ot  = tid & 63;
    const int rg  = ot >> 2;         // 0..15 : thread's rows are rg + 16*u
    const int cg  = ot & 3;          // 0..3  : gate (4 consecutive z-cols)
    const int j0  = bc * 4;
    const int gb  = tid >> 2;        // gate phase: batch row
    const int gj  = tid & 3;         // gate phase: unit offset
    const int bq  = ot >> 3;         // staging: row sub-index
    const int k4  = (ot & 7) * 4;    // staging: k offset within chunk

    for (int layer = 0; layer < 3; layer++) {
        const float* Wl = (layer == 0) ? W0 : ((layer == 1) ? W1 : W2);
        const float* Ul = (layer == 0) ? U0 : ((layer == 1) ? U1 : U2);
        const float* bl = (layer == 0) ? b0 : ((layer == 1) ? b1 : b2);
        const float* xsrc = (layer == 0) ? x0 : ((layer == 1) ? g_seqA : g_seqB);
        float* seqout = (layer == 0) ? g_seqA : ((layer == 1) ? g_seqB : (float*)0);
        const int K_in = (layer == 0) ? Dsz : Hsz;
        const int Ktot = K_in + Hsz;        // 768 or 1024
        const int Kpg  = Ktot >> 2;         // per k-split group
        const int nch  = Kpg / KC;          // 6 or 8

        // ---- weights resident in smem for the whole layer (once) ----
        for (int idx = tid; idx < Ktot * 4; idx += NTHR) {
            int gk = idx >> 2, p = idx & 3;
            const float* wrow = (gk < K_in) ? (Wl + (size_t)gk * Gsz)
                                            : (Ul + (size_t)(gk - K_in) * Gsz);
            *(float4*)&w_s[gk * 16 + p * 4] = *(const float4*)(wrow + p * Hsz + j0);
        }
        if (tid < 16) bias_s[tid] = bl[(tid >> 2) * Hsz + j0 + (tid & 3)];
        g_hbuf[0][gb * Hsz + j0 + gj] = 0.0f;
        float c_reg = 0.0f, hval = 0.0f;
        int cur = 0;
        grid_sync();

        for (int t = 0; t < Tsz; t++) {
            const float* hsrc = g_hbuf[cur];
            float acc[4][4] = {};
            float4 st[8];

            // LDG one chunk into registers
            #define LDG_CHUNK(CC)                                                        \
                do {                                                                     \
                    int kb_ = ks * Kpg + (CC) * KC;                                      \
                    if (kb_ < K_in) {                                                    \
                        const float* s_ = xsrc + (size_t)t * K_in + kb_ + k4;            \
                        _Pragma("unroll")                                                \
                        for (int r_ = 0; r_ < 8; r_++)                                   \
                            st[r_] = *(const float4*)(s_ + (size_t)(r_ * 8 + bq) * Tsz * K_in); \
                    } else {                                                             \
                        const float* s_ = hsrc + (kb_ - K_in) + k4;                      \
                        _Pragma("unroll")                                                \
                        for (int r_ = 0; r_ < 8; r_++)                                   \
                            st[r_] = *(const float4*)(s_ + (r_ * 8 + bq) * Hsz);         \
                    }                                                                    \
                } while (0)

            LDG_CHUNK(0);

            for (int cc = 0; cc < nch; cc++) {
                // STS current chunk into buffer cc&1
                float* ad = a_s + (((cc & 1) * 4 + ks) * 64) * 36;
                #pragma unroll
                for (int r = 0; r < 8; r++)
                    *(float4*)&ad[(r * 8 + bq) * 36 + k4] = st[r];
                // prefetch next chunk
                if (cc + 1 < nch) LDG_CHUNK(cc + 1);
                __syncthreads();

                // compute chunk cc from buffer cc&1
                const float* ab = a_s + (((cc & 1) * 4 + ks) * 64) * 36;
                const float* wb = w_s + (ks * Kpg + cc * KC) * 16;
                #pragma unroll
                for (int kq = 0; kq < KC / 4; kq++) {
                    float4 w0 = *(const float4*)&wb[(kq * 4 + 0) * 16 + cg * 4];
                    float4 w1 = *(const float4*)&wb[(kq * 4 + 1) * 16 + cg * 4];
                    float4 w2 = *(const float4*)&wb[(kq * 4 + 2) * 16 + cg * 4];
                    float4 w3 = *(const float4*)&wb[(kq * 4 + 3) * 16 + cg * 4];
                    #pragma unroll
                    for (int u = 0; u < 4; u++) {
                        float4 a = *(const float4*)&ab[(rg + 16 * u) * 36 + kq * 4];
                        acc[u][0] += a.x * w0.x; acc[u][1] += a.x * w0.y;
                        acc[u][2] += a.x * w0.z; acc[u][3] += a.x * w0.w;
                        acc[u][0] += a.y * w1.x; acc[u][1] += a.y * w1.y;
                        acc[u][2] += a.y * w1.z; acc[u][3] += a.y * w1.w;
                        acc[u][0] += a.z * w2.x; acc[u][1] += a.z * w2.y;
                        acc[u][2] += a.z * w2.z; acc[u][3] += a.z * w2.w;
                        acc[u][0] += a.w * w3.x; acc[u][1] += a.w * w3.y;
                        acc[u][2] += a.w * w3.z; acc[u][3] += a.w * w3.w;
                    }
                }
            }
            #undef LDG_CHUNK

            // ---- k-split partials to smem ----
            #pragma unroll
            for (int u = 0; u < 4; u++)
                #pragma unroll
                for (int v = 0; v < 4; v++)
                    zred[ks * 1088 + (rg + 16 * u) * 17 + cg * 4 + v] = acc[u][v];
            __syncthreads();

            // ---- gather + gates: one thread per (batch gb, unit gj) ----
            {
                float z[4];
                #pragma unroll
                for (int g = 0; g < 4; g++) {
                    int c = g * 4 + gj;
                    int o = gb * 17 + c;
                    z[g] = zred[o] + zred[1088 + o] + zred[2176 + o] + zred[3264 + o]
                         + bias_s[c];
                }
                float ig = fsig(z[0]);
                float fg = fsig(z[1]);
                float gg = ftanh(z[2]);
                float og = fsig(z[3]);
                c_reg = fg * c_reg + ig * gg;
                hval  = og * ftanh(c_reg);
                g_hbuf[cur ^ 1][gb * Hsz + j0 + gj] = hval;
                if (seqout) seqout[((size_t)(gb * Tsz + t)) * Hsz + j0 + gj] = hval;
            }
            cur ^= 1;
            grid_sync();
        }

        // ---- layer finals. Output: [out(=h2) | h0 | c0 | h1 | c1 | h2 | c2] ----
        {
            size_t off = (size_t)gb * Hsz + j0 + gj;
            const size_t S = (size_t)Bsz * Hsz;
            if (layer == 0)      { out[1 * S + off] = hval; out[2 * S + off] = c_reg; }
            else if (layer == 1) { out[3 * S + off] = hval; out[4 * S + off] = c_reg; }
            else                 { out[off] = hval; out[5 * S + off] = hval; out[6 * S + off] = c_reg; }
        }
        grid_sync();
    }
}

extern "C" void kernel_launch(void* const* d_in, const int* in_sizes, int n_in,
                              void* d_out, int out_size) {
    (void)in_sizes; (void)n_in; (void)out_size;
    static int attr_done = 0;
    if (!attr_done) {
        cudaFuncSetAttribute(lstm_kernel,
                             cudaFuncAttributeMaxDynamicSharedMemorySize, SMEM_BYTES);
        attr_done = 1;
    }
    lstm_kernel<<<NBLK, NTHR, SMEM_BYTES>>>(
        (const float*)d_in[0],
        (const float*)d_in[1], (const float*)d_in[2], (const float*)d_in[3],
        (const float*)d_in[4], (const float*)d_in[5], (const float*)d_in[6],
        (const float*)d_in[7], (const float*)d_in[8], (const float*)d_in[9],
        (float*)d_out);
}

// round 4
// speedup vs baseline: 1.6031x; 1.0511x over previous
#include <cuda_runtime.h>

// Stacked LSTM: B=64, T=512, D=256, H=512, 3 layers. fp32.
// Persistent kernel, 128 blocks x 256 threads, one grid barrier per timestep.
// Block bc owns 4 hidden units => 16 z-columns. Per step: 64x16xK GEMM
// (K = D+H or 2H), 4-way K-split, 4x4 register tiles, packed f32x2 FFMA
// (fma.rn.f32x2: 2 MACs per fma-pipe issue on sm_103a).
// Weights resident in smem per layer. A panel double-buffered, chunk 0 of the
// next step (always x-region by strided chunk mapping) prefetched before the
// grid barrier.

#define Bsz 64
#define Tsz 512
#define Dsz 256
#define Hsz 512
#define Gsz 2048
#define NBLK 128
#define NTHR 256
#define KC 32

typedef unsigned long long u64;

// dynamic smem layout (floats):
//   w_s   [1024][16]              16384
//   a_s   [2][4][64][36]          18432
//   zred  [4][64][18]              4608
//   bias  [16]                       16
#define SM_WS   0
#define SM_AS   16384
#define SM_ZRED (16384 + 18432)
#define SM_BIAS (16384 + 18432 + 4608)
#define SMEM_FLOATS (16384 + 18432 + 4608 + 16)
#define SMEM_BYTES (SMEM_FLOATS * 4)

__device__ float g_seqA[(size_t)Bsz * Tsz * Hsz];  // 64 MB
__device__ float g_seqB[(size_t)Bsz * Tsz * Hsz];  // 64 MB
__device__ float g_hbuf[2][Bsz * Hsz];
__device__ unsigned g_count = 0;
__device__ volatile unsigned g_gen = 0;

__device__ __forceinline__ void grid_sync() {
    __threadfence();
    __syncthreads();
    if (threadIdx.x == 0) {
        unsigned my = g_gen;
        if (atomicAdd(&g_count, 1u) == NBLK - 1) {
            g_count = 0;
            __threadfence();
            atomicAdd((unsigned*)&g_gen, 1u);
        } else {
            while (g_gen == my) { __nanosleep(32); }
        }
    }
    __syncthreads();
}

__device__ __forceinline__ float fsig(float x) {
    return __fdividef(1.0f, 1.0f + __expf(-x));
}
__device__ __forceinline__ float ftanh(float x) {
    float e = __expf(2.0f * x);
    return 1.0f - __fdividef(2.0f, e + 1.0f);
}

// packed f32x2 helpers
__device__ __forceinline__ void fma2(u64& d, u64 a, u64 b) {
    asm("fma.rn.f32x2 %0, %1, %2, %0;" : "+l"(d) : "l"(a), "l"(b));
}
__device__ __forceinline__ u64 rep2(float x) {
    u64 r;
    asm("mov.b64 %0, {%1, %1};" : "=l"(r) : "f"(x));
    return r;
}

extern "C" __global__ void __launch_bounds__(NTHR, 1)
lstm_kernel(const float* __restrict__ x0,
            const float* __restrict__ W0, const float* __restrict__ U0, const float* __restrict__ b0,
            const float* __restrict__ W1, const float* __restrict__ U1, const float* __restrict__ b1,
            const float* __restrict__ W2, const float* __restrict__ U2, const float* __restrict__ b2,
            float* __restrict__ out)
{
    extern __shared__ float smem[];
    float* w_s    = smem + SM_WS;     // [k][16]
    float* a_s    = smem + SM_AS;     // [buf][ks][row][36]
    float* zred   = smem + SM_ZRED;   // [ks][row][18]
    float* bias_s = smem + SM_BIAS;   // [16]

    const int tid = threadIdx.x;
    const int bc  = blockIdx.x;
    const int ks  = tid >> 6;        // 0..3 K-split group
    const int ot  = tid & 63;
    const int rg  = ot >> 2;         // 0..15 : rows rg + 16*u
    const int cg  = ot & 3;          // 0..3  : gate (4 consecutive z-cols)
    const int j0  = bc * 4;
    const int gb  = tid >> 2;        // gate phase: batch row
    const int gj  = tid & 3;         // gate phase: unit offset
    const int bq  = ot >> 3;         // staging: row sub-index
    const int k4  = (ot & 7) * 4;    // staging: k offset within chunk

    for (int layer = 0; layer < 3; layer++) {
        const float* Wl = (layer == 0) ? W0 : ((layer == 1) ? W1 : W2);
        const float* Ul = (layer == 0) ? U0 : ((layer == 1) ? U1 : U2);
        const float* bl = (layer == 0) ? b0 : ((layer == 1) ? b1 : b2);
        const float* xsrc = (layer == 0) ? x0 : ((layer == 1) ? g_seqA : g_seqB);
        float* seqout = (layer == 0) ? g_seqA : ((layer == 1) ? g_seqB : (float*)0);
        const int K_in = (layer == 0) ? Dsz : Hsz;
        const int Ktot = K_in + Hsz;        // 768 or 1024
        const int nch  = Ktot / KC / 4;     // chunks per k-split group (6 or 8)

        // ---- weights resident in smem for the whole layer (once) ----
        for (int idx = tid; idx < Ktot * 4; idx += NTHR) {
            int gk = idx >> 2, p = idx & 3;
            const float* wrow = (gk < K_in) ? (Wl + (size_t)gk * Gsz)
                                            : (Ul + (size_t)(gk - K_in) * Gsz);
            *(float4*)&w_s[gk * 16 + p * 4] = *(const float4*)(wrow + p * Hsz + j0);
        }
        if (tid < 16) bias_s[tid] = bl[(tid >> 2) * Hsz + j0 + (tid & 3)];
        g_hbuf[0][gb * Hsz + j0 + gj] = 0.0f;
        float c_reg = 0.0f, hval = 0.0f;
        int cur = 0;

        float4 st[8];
        // Strided chunk mapping: chunk cc of group ks covers k-base
        // (cc*4 + ks)*KC. Chunk 0 is always in the x region (no h dep).
        #define LDG_CHUNK(TT, CC)                                                        \
            do {                                                                         \
                int kb_ = ((CC) * 4 + ks) * KC;                                          \
                if (kb_ < K_in) {                                                        \
                    const float* s_ = xsrc + (size_t)(TT) * K_in + kb_ + k4;             \
                    _Pragma("unroll")                                                    \
                    for (int r_ = 0; r_ < 8; r_++)                                       \
                        st[r_] = *(const float4*)(s_ + (size_t)(r_ * 8 + bq) * Tsz * K_in); \
                } else {                                                                 \
                    const float* s_ = hsrc + (kb_ - K_in) + k4;                          \
                    _Pragma("unroll")                                                    \
                    for (int r_ = 0; r_ < 8; r_++)                                       \
                        st[r_] = *(const float4*)(s_ + (r_ * 8 + bq) * Hsz);             \
                }                                                                        \
            } while (0)

        {   // prefetch step-0 chunk-0 (x region, pre-barrier safe)
            const float* hsrc = g_hbuf[0];
            LDG_CHUNK(0, 0);
        }
        grid_sync();

        for (int t = 0; t < Tsz; t++) {
            const float* hsrc = g_hbuf[cur];
            u64 acc[4][2] = {};

            for (int cc = 0; cc < nch; cc++) {
                // STS current chunk into buffer cc&1
                float* ad = a_s + (((cc & 1) * 4 + ks) * 64) * 36;
                #pragma unroll
                for (int r = 0; r < 8; r++)
                    *(float4*)&ad[(r * 8 + bq) * 36 + k4] = st[r];
                // prefetch next chunk
                if (cc + 1 < nch) LDG_CHUNK(t, cc + 1);
                __syncthreads();

                // compute chunk cc (packed f32x2: col pairs)
                const float* ab = a_s + (((cc & 1) * 4 + ks) * 64) * 36;
                const float* wb = w_s + ((cc * 4 + ks) * KC) * 16;
                #pragma unroll
                for (int kq = 0; kq < KC / 4; kq++) {
                    ulonglong2 w0 = *(const ulonglong2*)&wb[(kq * 4 + 0) * 16 + cg * 4];
                    ulonglong2 w1 = *(const ulonglong2*)&wb[(kq * 4 + 1) * 16 + cg * 4];
                    ulonglong2 w2 = *(const ulonglong2*)&wb[(kq * 4 + 2) * 16 + cg * 4];
                    ulonglong2 w3 = *(const ulonglong2*)&wb[(kq * 4 + 3) * 16 + cg * 4];
                    #pragma unroll
                    for (int u = 0; u < 4; u++) {
                        float4 a = *(const float4*)&ab[(rg + 16 * u) * 36 + kq * 4];
                        u64 a0 = rep2(a.x), a1 = rep2(a.y), a2 = rep2(a.z), a3 = rep2(a.w);
                        fma2(acc[u][0], a0, w0.x); fma2(acc[u][1], a0, w0.y);
                        fma2(acc[u][0], a1, w1.x); fma2(acc[u][1], a1, w1.y);
                        fma2(acc[u][0], a2, w2.x); fma2(acc[u][1], a2, w2.y);
                        fma2(acc[u][0], a3, w3.x); fma2(acc[u][1], a3, w3.y);
                    }
                }
            }

            // ---- k-split partials to smem (float2 stores) ----
            #pragma unroll
            for (int u = 0; u < 4; u++) {
                #pragma unroll
                for (int p = 0; p < 2; p++) {
                    *(float2*)&zred[ks * 1152 + (rg + 16 * u) * 18 + cg * 4 + p * 2] =
                        *(float2*)&acc[u][p];
                }
            }
            __syncthreads();

            // ---- gather + gates: one thread per (batch gb, unit gj) ----
            {
                float z[4];
                #pragma unroll
                for (int g = 0; g < 4; g++) {
                    int o = gb * 18 + g * 4 + gj;
                    z[g] = zred[o] + zred[1152 + o] + zred[2304 + o] + zred[3456 + o]
                         + bias_s[g * 4 + gj];
                }
                float ig = fsig(z[0]);
                float fg = fsig(z[1]);
                float gg = ftanh(z[2]);
                float og = fsig(z[3]);
                c_reg = fg * c_reg + ig * gg;
                hval  = og * ftanh(c_reg);
                g_hbuf[cur ^ 1][gb * Hsz + j0 + gj] = hval;
                if (seqout) seqout[((size_t)(gb * Tsz + t)) * Hsz + j0 + gj] = hval;
            }
            cur ^= 1;

            // prefetch next step's chunk 0 (x region: no dependence on the
            // h being published at the upcoming barrier)
            if (t + 1 < Tsz) LDG_CHUNK(t + 1, 0);
            grid_sync();
        }
        #undef LDG_CHUNK

        // ---- layer finals. Output: [out(=h2) | h0 | c0 | h1 | c1 | h2 | c2] ----
        {
            size_t off = (size_t)gb * Hsz + j0 + gj;
            const size_t S = (size_t)Bsz * Hsz;
            if (layer == 0)      { out[1 * S + off] = hval; out[2 * S + off] = c_reg; }
            else if (layer == 1) { out[3 * S + off] = hval; out[4 * S + off] = c_reg; }
            else                 { out[off] = hval; out[5 * S + off] = hval; out[6 * S + off] = c_reg; }
        }
        grid_sync();
    }
}

extern "C" void kernel_launch(void* const* d_in, const int* in_sizes, int n_in,
                              void* d_out, int out_size) {
    (void)in_sizes; (void)n_in; (void)out_size;
    static int attr_done = 0;
    if (!attr_done) {
        cudaFuncSetAttribute(lstm_kernel,
                             cudaFuncAttributeMaxDynamicSharedMemorySize, SMEM_BYTES);
        attr_done = 1;
    }
    lstm_kernel<<<NBLK, NTHR, SMEM_BYTES>>>(
        (const float*)d_in[0],
        (const float*)d_in[1], (const float*)d_in[2], (const float*)d_in[3],
        (const float*)d_in[4], (const float*)d_in[5], (const float*)d_in[6],
        (const float*)d_in[7], (const float*)d_in[8], (const float*)d_in[9],
        (float*)d_out);
}

// round 5
// speedup vs baseline: 1.7313x; 1.0800x over previous
#include <cuda_runtime.h>

// Stacked LSTM: B=64, T=512, D=256, H=512, 3 layers. fp32.
// Persistent kernel, 128 blocks x 512 threads (16 warps), split-phase grid
// barrier per timestep. Block bc owns 4 hidden units => 16 z-columns.
// Per step: 64x16xK GEMM (K = D+H or 2H), K split 16 ways (one warp each),
// 4x8 thread tiles, packed f32x2 FFMA. Weights resident in smem per layer.
// A panel staged in 256-k "superchunks" (block-wide coalesced LDG->STS,
// register prefetch). x-region superchunks of each step are computed between
// barrier arrive and wait, hiding barrier latency.

#define Bsz 64
#define Tsz 512
#define Dsz 256
#define Hsz 512
#define Gsz 2048
#define NBLK 128
#define NTHR 512

typedef unsigned long long u64;

// dynamic smem (floats):
//   w_s   [1024][16]   16384
//   a_s   [64][260]    16640   (one 256-k superchunk, row stride 260: 1040B, mod128=16)
//   zred  [16][64][18] 18432
//   bias  [16]            16
#define SM_WS   0
#define SM_AS   16384
#define SM_ZRED (16384 + 16640)
#define SM_BIAS (16384 + 16640 + 18432)
#define SMEM_FLOATS (16384 + 16640 + 18432 + 16)
#define SMEM_BYTES (SMEM_FLOATS * 4)

__device__ float g_seqA[(size_t)Bsz * Tsz * Hsz];
__device__ float g_seqB[(size_t)Bsz * Tsz * Hsz];
__device__ float g_hbuf[2][Bsz * Hsz];
__device__ unsigned g_count = 0;
__device__ unsigned g_gen = 0;

// ---- split-phase grid barrier (snapshot-based; replay-safe) ----
__device__ __forceinline__ void bar_arrive(unsigned* s_my) {
    __syncthreads();                      // block's writes done
    if (threadIdx.x == 0) {
        unsigned my;
        asm volatile("ld.relaxed.gpu.u32 %0, [%1];" : "=r"(my) : "l"(&g_gen));
        *s_my = my;
        __threadfence();                  // release this block's writes
        unsigned old = atomicAdd(&g_count, 1u);
        if (old == NBLK - 1) {
            g_count = 0;
            __threadfence();
            asm volatile("st.release.gpu.u32 [%0], %1;" :: "l"(&g_gen), "r"(my + 1u));
        }
    }
}
__device__ __forceinline__ void bar_wait(unsigned* s_my) {
    if (threadIdx.x == 0) {
        unsigned my = *s_my, g;
        do {
            asm volatile("ld.acquire.gpu.u32 %0, [%1];" : "=r"(g) : "l"(&g_gen));
        } while (g == my);
    }
    __syncthreads();                      // all threads see released state
}

__device__ __forceinline__ float fsig(float x) {
    return __fdividef(1.0f, 1.0f + __expf(-x));
}
__device__ __forceinline__ float ftanh(float x) {
    float e = __expf(2.0f * x);
    return 1.0f - __fdividef(2.0f, e + 1.0f);
}
__device__ __forceinline__ void fma2(u64& d, u64 a, u64 b) {
    asm("fma.rn.f32x2 %0, %1, %2, %0;" : "+l"(d) : "l"(a), "l"(b));
}
__device__ __forceinline__ u64 rep2(float x) {
    u64 r;
    asm("mov.b64 %0, {%1, %1};" : "=l"(r) : "f"(x));
    return r;
}

extern "C" __global__ void __launch_bounds__(NTHR, 1)
lstm_kernel(const float* __restrict__ x0,
            const float* __restrict__ W0, const float* __restrict__ U0, const float* __restrict__ b0,
            const float* __restrict__ W1, const float* __restrict__ U1, const float* __restrict__ b1,
            const float* __restrict__ W2, const float* __restrict__ U2, const float* __restrict__ b2,
            float* __restrict__ out)
{
    extern __shared__ float smem[];
    float* w_s    = smem + SM_WS;     // [k][16]
    float* a_s    = smem + SM_AS;     // [64][260]
    float* zred   = smem + SM_ZRED;   // [16][64][18]
    float* bias_s = smem + SM_BIAS;   // [16]
    __shared__ unsigned s_my;

    const int tid = threadIdx.x;
    const int bc  = blockIdx.x;
    const int j0  = bc * 4;
    // compute mapping: warp = k-split group
    const int ks   = tid >> 5;        // 0..15
    const int lane = tid & 31;
    const int rg   = lane >> 1;       // 0..15 : rows rg + 16u, u<4
    const int cgp  = lane & 1;        // 0..1  : cols cgp*8 .. +7
    // staging mapping
    const int kq4  = (tid & 63) * 4;  // k offset within superchunk (0..252)
    const int r0   = tid >> 6;        // 0..7  : rows r0 + 8*rep
    // gate mapping (tid < 256)
    const int gb = tid >> 2;
    const int gj = tid & 3;

    for (int layer = 0; layer < 3; layer++) {
        const float* Wl = (layer == 0) ? W0 : ((layer == 1) ? W1 : W2);
        const float* Ul = (layer == 0) ? U0 : ((layer == 1) ? U1 : U2);
        const float* bl = (layer == 0) ? b0 : ((layer == 1) ? b1 : b2);
        const float* xsrc = (layer == 0) ? x0 : ((layer == 1) ? g_seqA : g_seqB);
        float* seqout = (layer == 0) ? g_seqA : ((layer == 1) ? g_seqB : (float*)0);
        const int K_in = (layer == 0) ? Dsz : Hsz;
        const int Ktot = K_in + Hsz;        // 768 or 1024
        const int nsc  = Ktot >> 8;         // superchunks: 3 or 4
        const int nx   = K_in >> 8;         // x-region superchunks: 1 or 2

        // ---- weights resident in smem (once per layer) ----
        for (int idx = tid; idx < Ktot * 4; idx += NTHR) {
            int gk = idx >> 2, p = idx & 3;
            const float* wrow = (gk < K_in) ? (Wl + (size_t)gk * Gsz)
                                            : (Ul + (size_t)(gk - K_in) * Gsz);
            *(float4*)&w_s[gk * 16 + p * 4] = *(const float4*)(wrow + p * Hsz + j0);
        }
        if (tid < 16) bias_s[tid] = bl[(tid >> 2) * Hsz + j0 + (tid & 3)];
        float c_reg = 0.0f, hval = 0.0f;
        if (tid < 256) g_hbuf[0][gb * Hsz + j0 + gj] = 0.0f;
        int cur = 0;
        bar_arrive(&s_my);   // publishes zeroed h_0 slice

        float4 st[8];
        // stage superchunk SC of step TT into registers (coalesced 512B rows)
        #define LDG_SC(TT, SC)                                                        \
            do {                                                                      \
                if ((SC) < nx) {                                                      \
                    const float* s_ = xsrc + (size_t)(TT) * K_in + (SC) * 256 + kq4;  \
                    _Pragma("unroll")                                                 \
                    for (int r_ = 0; r_ < 8; r_++)                                    \
                        st[r_] = *(const float4*)(s_ + (size_t)(r0 + 8 * r_) * Tsz * K_in); \
                } else {                                                              \
                    const float* s_ = hsrc + ((SC) * 256 - K_in) + kq4;               \
                    _Pragma("unroll")                                                 \
                    for (int r_ = 0; r_ < 8; r_++)                                    \
                        st[r_] = *(const float4*)(s_ + (r0 + 8 * r_) * Hsz);          \
                }                                                                     \
            } while (0)

        #define STS_SC()                                                              \
            do {                                                                      \
                _Pragma("unroll")                                                     \
                for (int r_ = 0; r_ < 8; r_++)                                        \
                    *(float4*)&a_s[(r0 + 8 * r_) * 260 + kq4] = st[r_];               \
            } while (0)

        // compute this warp's 16-k slice of superchunk SC
        #define COMPUTE_SC(SC)                                                        \
            do {                                                                      \
                const float* wb = w_s + ((SC) * 256 + ks * 16) * 16;                  \
                const float* ab = a_s + ks * 16;                                      \
                _Pragma("unroll")                                                     \
                for (int kq = 0; kq < 4; kq++) {                                      \
                    float av[4][4];                                                   \
                    _Pragma("unroll")                                                 \
                    for (int u = 0; u < 4; u++)                                       \
                        *(float4*)av[u] = *(const float4*)&ab[(rg + 16 * u) * 260 + kq * 4]; \
                    _Pragma("unroll")                                                 \
                    for (int j = 0; j < 4; j++) {                                     \
                        const float* wr = wb + (kq * 4 + j) * 16 + cgp * 8;           \
                        ulonglong2 wlo = *(const ulonglong2*)wr;                      \
                        ulonglong2 whi = *(const ulonglong2*)(wr + 4);                \
                        _Pragma("unroll")                                             \
                        for (int u = 0; u < 4; u++) {                                 \
                            u64 ar = rep2(av[u][j]);                                  \
                            fma2(acc[u][0], ar, wlo.x);                               \
                            fma2(acc[u][1], ar, wlo.y);                               \
                            fma2(acc[u][2], ar, whi.x);                               \
                            fma2(acc[u][3], ar, whi.y);                               \
                        }                                                             \
                    }                                                                 \
                }                                                                     \
            } while (0)

        {
            const float* hsrc = g_hbuf[0];
            LDG_SC(0, 0);   // step-0 x superchunk (barrier-independent)
            (void)hsrc;
        }

        for (int t = 0; t < Tsz; t++) {
            const float* hsrc = g_hbuf[cur];
            u64 acc[4][4] = {};

            // ---- x-phase (overlaps other blocks' barrier arrival) ----
            for (int sc = 0; sc < nx; sc++) {
                STS_SC();
                if (sc + 1 < nx) LDG_SC(t, sc + 1);
                __syncthreads();
                COMPUTE_SC(sc);
                __syncthreads();
            }

            // ---- wait for h_t, then h-phase ----
            bar_wait(&s_my);
            LDG_SC(t, nx);
            for (int sc = nx; sc < nsc; sc++) {
                STS_SC();
                if (sc + 1 < nsc) LDG_SC(t, sc + 1);
                __syncthreads();
                COMPUTE_SC(sc);
                __syncthreads();
            }

            // ---- k-split partials ----
            #pragma unroll
            for (int u = 0; u < 4; u++)
                #pragma unroll
                for (int p = 0; p < 4; p++)
                    *(float2*)&zred[ks * 1152 + (rg + 16 * u) * 18 + cgp * 8 + p * 2] =
                        *(float2*)&acc[u][p];
            __syncthreads();

            // ---- gather + gates (tid < 256: one thread per (b, j)) ----
            if (tid < 256) {
                float z[4];
                #pragma unroll
                for (int g = 0; g < 4; g++) {
                    int c = g * 4 + gj;
                    float s = bias_s[c];
                    #pragma unroll
                    for (int k = 0; k < 16; k++)
                        s += zred[k * 1152 + gb * 18 + c];
                    z[g] = s;
                }
                float ig = fsig(z[0]);
                float fg = fsig(z[1]);
                float gg = ftanh(z[2]);
                float og = fsig(z[3]);
                c_reg = fg * c_reg + ig * gg;
                hval  = og * ftanh(c_reg);
                g_hbuf[cur ^ 1][gb * Hsz + j0 + gj] = hval;
                if (seqout) seqout[((size_t)(gb * Tsz + t)) * Hsz + j0 + gj] = hval;
            }
            cur ^= 1;

            bar_arrive(&s_my);               // publish h_{t+1}
            if (t + 1 < Tsz) LDG_SC(t + 1, 0);  // prefetch next x superchunk
        }
        bar_wait(&s_my);   // full barrier: layer complete everywhere

        // ---- layer finals. Output: [out(=h2) | h0 | c0 | h1 | c1 | h2 | c2] ----
        if (tid < 256) {
            size_t off = (size_t)gb * Hsz + j0 + gj;
            const size_t S = (size_t)Bsz * Hsz;
            if (layer == 0)      { out[1 * S + off] = hval; out[2 * S + off] = c_reg; }
            else if (layer == 1) { out[3 * S + off] = hval; out[4 * S + off] = c_reg; }
            else                 { out[off] = hval; out[5 * S + off] = hval; out[6 * S + off] = c_reg; }
        }
        #undef LDG_SC
        #undef STS_SC
        #undef COMPUTE_SC
    }
}

extern "C" void kernel_launch(void* const* d_in, const int* in_sizes, int n_in,
                              void* d_out, int out_size) {
    (void)in_sizes; (void)n_in; (void)out_size;
    static int attr_done = 0;
    if (!attr_done) {
        cudaFuncSetAttribute(lstm_kernel,
                             cudaFuncAttributeMaxDynamicSharedMemorySize, SMEM_BYTES);
        attr_done = 1;
    }
    lstm_kernel<<<NBLK, NTHR, SMEM_BYTES>>>(
        (const float*)d_in[0],
        (const float*)d_in[1], (const float*)d_in[2], (const float*)d_in[3],
        (const float*)d_in[4], (const float*)d_in[5], (const float*)d_in[6],
        (const float*)d_in[7], (const float*)d_in[8], (const float*)d_in[9],
        (float*)d_out);
}